// round 6
// baseline (speedup 1.0000x reference)
#include <cuda_runtime.h>
#include <cuda_bf16.h>
#include <math.h>
#include <stdint.h>

// Problem constants
#define B_ 256
#define T_ 2048
#define C_ 12
#define K_ 4
#define L_ 8
#define FEAT_ 64
#define HID_ 128
#define NCLS_ 10
#define N2_ 1024
#define TR_ 1025
#define EPS_ 1e-5f
#define NBMAX_ 16

typedef unsigned long long ull;

// ---------------------------------------------------------------------------
// Device scratch (static; no runtime allocation)
// ---------------------------------------------------------------------------
__device__ float g_filt[K_ * TR_];
__device__ float d_modes[(size_t)K_ * B_ * C_ * T_];             // 96 MB
__device__ float d_h1[(size_t)K_ * B_ * 32 * T_];                // 256 MB
__device__ float d_h2[(size_t)K_ * B_ * 64 * T_];                // 512 MB
__device__ float d_h3[(size_t)K_ * B_ * 64 * T_];                // 512 MB
__device__ float d_psum[(size_t)K_ * 64 * B_ * NBMAX_];
__device__ float d_psq[(size_t)K_ * 64 * B_ * NBMAX_];
__device__ float d_mean[K_ * 64];
__device__ float d_rstd[K_ * 64];
__device__ float d_feats[B_ * K_ * FEAT_];
// weight pairs (w,w), layout [km][ci*KS+dk][co]
__device__ __align__(16) ull d_w2_1[K_ * 12 * 7 * 32];
__device__ __align__(16) ull d_w2_2[K_ * 32 * 5 * 64];
__device__ __align__(16) ull d_w2_3[K_ * 64 * 3 * 64];

// ---------------------------------------------------------------------------
// Packed f32x2 helpers
// ---------------------------------------------------------------------------
__device__ __forceinline__ ull pack2(float lo, float hi) {
    ull r; asm("mov.b64 %0, {%1, %2};" : "=l"(r) : "f"(lo), "f"(hi)); return r;
}
__device__ __forceinline__ float2 u2f(ull v) {
    float2 f; asm("mov.b64 {%0, %1}, %2;" : "=f"(f.x), "=f"(f.y) : "l"(v)); return f;
}
__device__ __forceinline__ ull fma2(ull a, ull b, ull c) {
    ull d; asm("fma.rn.f32x2 %0, %1, %2, %3;" : "=l"(d) : "l"(a), "l"(b), "l"(c)); return d;
}
__device__ __forceinline__ ull add2(ull a, ull b) {
    ull d; asm("add.rn.f32x2 %0, %1, %2;" : "=l"(d) : "l"(a), "l"(b)); return d;
}

// ---------------------------------------------------------------------------
// 1. UVMD frequency-domain filters g_k(f) (scan is linear in f_hat).
// ---------------------------------------------------------------------------
__device__ __forceinline__ float softplusf(float x) {
    if (x > 20.f) return x;
    return log1pf(expf(x));
}

__global__ __launch_bounds__(128) void g_kernel(
        const float* __restrict__ log_alpha,
        const float* __restrict__ raw_tau,
        const float* __restrict__ raw_omega) {
    float om[K_];
#pragma unroll
    for (int k = 0; k < K_; k++) om[k] = 0.5f / (1.0f + expf(-raw_omega[k]));
    int f = blockIdx.x * blockDim.x + threadIdx.x;
    if (f >= TR_) return;
    float fr = 0.5f * (float)f / 1024.0f;
    float u[K_] = {0.f, 0.f, 0.f, 0.f};
    float lam = 0.f;
    for (int l = 0; l < L_; l++) {
        float tau_l = softplusf(raw_tau[l]);
        float us = u[0] + u[1] + u[2] + u[3];
        float nu[K_], ns = 0.f;
#pragma unroll
        for (int k = 0; k < K_; k++) {
            float a = expf(log_alpha[l * K_ + k]);
            float d = fr - om[k];
            float num = 1.0f - (us - u[k]) + 0.5f * lam;
            nu[k] = num / (1.0f + 2.0f * a * d * d);
            ns += nu[k];
        }
#pragma unroll
        for (int k = 0; k < K_; k++) u[k] = nu[k];
        lam += tau_l * (1.0f - ns);
    }
#pragma unroll
    for (int k = 0; k < K_; k++) g_filt[k * TR_ + f] = u[k];
}

// ---------------------------------------------------------------------------
// 2. Fused rfft -> filter -> irfft per (b,c) signal; writes modes (K,B,C,T).
// ---------------------------------------------------------------------------
__device__ __forceinline__ void fft1024(float* zr, float* zi,
                                        const float* twr, const float* twi,
                                        float dir, int tid) {
#pragma unroll
    for (int s = 0; s < 10; s++) {
        int half = 1 << s;
        int shift = 9 - s;
#pragma unroll
        for (int rep = 0; rep < 2; rep++) {
            int i = tid + rep * 256;
            int pos = i & (half - 1);
            int blk = i >> s;
            int i1 = (blk << (s + 1)) + pos;
            int i2 = i1 + half;
            int ti = pos << shift;
            float c = twr[ti];
            float sn = dir * twi[ti];
            float x2r = zr[i2], x2i = zi[i2];
            float tr = c * x2r - sn * x2i;
            float tim = sn * x2r + c * x2i;
            float x1r = zr[i1], x1i = zi[i1];
            zr[i2] = x1r - tr; zi[i2] = x1i - tim;
            zr[i1] = x1r + tr; zi[i1] = x1i + tim;
        }
        __syncthreads();
    }
}

__global__ __launch_bounds__(256) void uvmd_kernel(const float* __restrict__ x) {
    __shared__ float twr[512], twi[512];
    __shared__ float zr[N2_], zi[N2_];
    __shared__ float Xr[TR_], Xi[TR_];
    int tid = threadIdx.x;
    int sig = blockIdx.x;
    int b = sig / C_, c = sig % C_;

    for (int j = tid; j < 512; j += 256) {
        float ang = (float)M_PI * (float)j / 512.0f;
        twr[j] = cosf(ang);
        twi[j] = -sinf(ang);
    }
    const float* xb = x + (size_t)b * T_ * C_ + c;
    for (int n = tid; n < N2_; n += 256) {
        int j = __brev((unsigned)n) >> 22;
        zr[n] = xb[(size_t)(2 * j) * C_];
        zi[n] = xb[(size_t)(2 * j + 1) * C_];
    }
    __syncthreads();
    fft1024(zr, zi, twr, twi, 1.0f, tid);

    for (int k = tid; k < N2_; k += 256) {
        if (k == 0) {
            Xr[0] = zr[0] + zi[0];   Xi[0] = 0.f;
            Xr[N2_] = zr[0] - zi[0]; Xi[N2_] = 0.f;
        } else {
            float ar = zr[k], ai = zi[k];
            float br = zr[N2_ - k], bi = -zi[N2_ - k];
            float er = 0.5f * (ar + br), ei = 0.5f * (ai + bi);
            float dr = 0.5f * (ar - br), di = 0.5f * (ai - bi);
            float or_ = di, oi = -dr;
            float s_, c_;
            __sincosf(-(float)M_PI * (float)k / 1024.0f, &s_, &c_);
            Xr[k] = er + c_ * or_ - s_ * oi;
            Xi[k] = ei + s_ * or_ + c_ * oi;
        }
    }
    __syncthreads();

    const float invn = 1.0f / 1024.0f;
    for (int km = 0; km < K_; km++) {
        const float* g = g_filt + km * TR_;
        for (int n = tid; n < N2_; n += 256) {
            int k = __brev((unsigned)n) >> 22;
            float vr, vi;
            if (k == 0) {
                float y0 = g[0] * Xr[0];
                float y1 = g[N2_] * Xr[N2_];
                vr = 0.5f * (y0 + y1);
                vi = 0.5f * (y0 - y1);
            } else {
                float gk = g[k], gm = g[N2_ - k];
                float yr = gk * Xr[k], yi = gk * Xi[k];
                float mr = gm * Xr[N2_ - k], mi = -(gm * Xi[N2_ - k]);
                float er = 0.5f * (yr + mr), ei = 0.5f * (yi + mi);
                float dr = 0.5f * (yr - mr), di = 0.5f * (yi - di * 0.f - di);
                // NOTE: keep exact original math below
                dr = 0.5f * (yr - mr); di = 0.5f * (yi - mi);
                float s_, c_;
                __sincosf((float)M_PI * (float)k / 1024.0f, &s_, &c_);
                float or_ = c_ * dr - s_ * di;
                float oi  = s_ * dr + c_ * di;
                vr = er - oi;
                vi = ei + or_;
            }
            zr[n] = vr; zi[n] = vi;
        }
        __syncthreads();
        fft1024(zr, zi, twr, twi, -1.0f, tid);
        float* orow = d_modes + ((((size_t)km * B_ + b) * C_ + c)) * T_;
        for (int n = tid; n < N2_; n += 256) {
            float2 v = make_float2(zr[n] * invn, zi[n] * invn);
            *reinterpret_cast<float2*>(orow + 2 * n) = v;
        }
        __syncthreads();
    }
}

// ---------------------------------------------------------------------------
// 2b. Weight repack: (w,w) pairs in layout [km][ci*KS+dk][co].
// ---------------------------------------------------------------------------
template <int CIN, int COUT, int KS>
__device__ __forceinline__ void wrepack_one(const float* __restrict__ w,
                                            ull* __restrict__ dst, int i) {
    const int n = K_ * CIN * KS * COUT;
    if (i >= n) return;
    int km = i / (CIN * KS * COUT);
    int r = i % (CIN * KS * COUT);
    int tap = r / COUT;
    int co = r % COUT;
    int ci = tap / KS;
    int dk = tap % KS;
    float v = w[(((size_t)km * COUT + co) * CIN + ci) * KS + dk];
    dst[i] = pack2(v, v);
}

__global__ __launch_bounds__(256) void wprep_kernel(
    const float* __restrict__ w1, const float* __restrict__ w2,
    const float* __restrict__ w3) {
    int i = blockIdx.x * blockDim.x + threadIdx.x;
    wrepack_one<12, 32, 7>(w1, d_w2_1, i);
    wrepack_one<32, 64, 5>(w2, d_w2_2, i);
    wrepack_one<64, 64, 3>(w3, d_w2_3, i);
}

// ---------------------------------------------------------------------------
// 3. Conv1d: adjacent-pair clusters, LDS.128 input fetch, f32x2 math.
//    Each thread: CO channels x 8 t = CO x 4 pairs as 2 clusters
//    {2h,2h+1} and {2h+P/2, 2h+P/2+1} (P = TILE/2 pairs).
//    Fused input BN+ReLU + fused BN-stat partials.
//    blockDim = (COUT/CO) * (TILE/8) = 256. gridDim = (T/TILE, B, K).
// ---------------------------------------------------------------------------
template <int CIN, int COUT, int KS, int CO, int TILE, int NB>
__global__ __launch_bounds__(256) void conv_kernel(
    const float* __restrict__ in, const ull* __restrict__ w2g,
    const float* __restrict__ bias,
    const float* __restrict__ bng, const float* __restrict__ bnb,
    const float* __restrict__ mean, const float* __restrict__ rstd,
    float* __restrict__ out, float* __restrict__ psum, float* __restrict__ psq,
    int apply_bn)
{
    constexpr int G = TILE / 8;         // threads per co-group
    constexpr int PAD = KS / 2;
    constexpr int IW = TILE + KS - 1;
    constexpr int IWP = ((TILE + 12 + 3) & ~3) > ((IW + 3) & ~3)
                        ? ((TILE + 12 + 3) & ~3) : ((IW + 3) & ~3);
    constexpr int NF4 = (KS + 6) / 4;   // float4 loads per cluster
    constexpr int NPRC = KS + 2;        // operand pairs per cluster
    __shared__ __align__(16) float s_in[CIN][IWP];
    __shared__ float s_a[CIN], s_c[CIN];

    int tx = threadIdx.x;
    int b = blockIdx.y;
    int km = blockIdx.z;
    int t0 = blockIdx.x * TILE;
    const float* inb = in + (((size_t)km * B_ + b) * CIN) * T_;

    if (apply_bn) {
        for (int ci = tx; ci < CIN; ci += 256) {
            float a = bng[km * CIN + ci] * rstd[km * 64 + ci];
            s_a[ci] = a;
            s_c[ci] = bnb[km * CIN + ci] - a * mean[km * 64 + ci];
        }
        __syncthreads();
    }
    for (int idx = tx; idx < CIN * IW; idx += 256) {
        int ci = idx / IW, tl = idx % IW;
        int t = t0 + tl - PAD;
        float v = 0.f;
        if (t >= 0 && t < T_) {
            v = inb[(size_t)ci * T_ + t];
            if (apply_bn) v = fmaxf(fmaf(s_a[ci], v, s_c[ci]), 0.f);
        }
        s_in[ci][tl] = v;
    }
    __syncthreads();

    int h = tx % G;
    int cog = tx / G;
    int co0 = cog * CO;
    int tb0 = 4 * h;                    // cluster 0 float base
    int tb1 = 4 * h + TILE / 2;         // cluster 1 float base

    ull acc[CO][4];                     // [co][cluster*2 + pair]
#pragma unroll
    for (int co = 0; co < CO; co++) {
        float bsv = bias[km * COUT + co0 + co];
        ull bi = pack2(bsv, bsv);
#pragma unroll
        for (int p = 0; p < 4; p++) acc[co][p] = bi;
    }

    const ull* wb = w2g + (size_t)km * CIN * KS * COUT + co0;
    for (int ci = 0; ci < CIN; ci++) {
        // fetch both clusters' input windows as float4s, build operand pairs
        float f0[NF4 * 4], f1[NF4 * 4];
        {
            const float4* p0 = reinterpret_cast<const float4*>(&s_in[ci][tb0]);
            const float4* p1 = reinterpret_cast<const float4*>(&s_in[ci][tb1]);
#pragma unroll
            for (int q = 0; q < NF4; q++) {
                float4 v0 = p0[q], v1 = p1[q];
                f0[4 * q] = v0.x; f0[4 * q + 1] = v0.y;
                f0[4 * q + 2] = v0.z; f0[4 * q + 3] = v0.w;
                f1[4 * q] = v1.x; f1[4 * q + 1] = v1.y;
                f1[4 * q + 2] = v1.z; f1[4 * q + 3] = v1.w;
            }
        }
        ull pr0[NPRC], pr1[NPRC];
#pragma unroll
        for (int j = 0; j < NPRC; j++) {
            pr0[j] = pack2(f0[j], f0[j + 1]);
            pr1[j] = pack2(f1[j], f1[j + 1]);
        }
        const ull* wci = wb + (size_t)ci * KS * COUT;
#pragma unroll
        for (int dk = 0; dk < KS; dk++) {
            ull w[CO];
#pragma unroll
            for (int hh = 0; hh < CO / 2; hh++) {
                ulonglong2 wp = __ldg(reinterpret_cast<const ulonglong2*>(
                    wci + (size_t)dk * COUT + 2 * hh));
                w[2 * hh] = wp.x;
                w[2 * hh + 1] = wp.y;
            }
#pragma unroll
            for (int co = 0; co < CO; co++) {
                acc[co][0] = fma2(pr0[dk], w[co], acc[co][0]);
                acc[co][1] = fma2(pr0[dk + 2], w[co], acc[co][1]);
                acc[co][2] = fma2(pr1[dk], w[co], acc[co][2]);
                acc[co][3] = fma2(pr1[dk + 2], w[co], acc[co][3]);
            }
        }
    }

    // epilogue: store pre-BN outputs (STG.128) + per-channel stats partials
#pragma unroll
    for (int co = 0; co < CO; co++) {
        float* op = out + (((size_t)km * B_ + b) * COUT + co0 + co) * T_ + t0;
        float2 a0 = u2f(acc[co][0]), a1 = u2f(acc[co][1]);
        float2 a2 = u2f(acc[co][2]), a3 = u2f(acc[co][3]);
        *reinterpret_cast<float4*>(op + tb0) = make_float4(a0.x, a0.y, a1.x, a1.y);
        *reinterpret_cast<float4*>(op + tb1) = make_float4(a2.x, a2.y, a3.x, a3.y);
        ull ssum = add2(add2(acc[co][0], acc[co][1]),
                        add2(acc[co][2], acc[co][3]));
        ull qsum = fma2(acc[co][0], acc[co][0], (ull)0);
        qsum = fma2(acc[co][1], acc[co][1], qsum);
        qsum = fma2(acc[co][2], acc[co][2], qsum);
        qsum = fma2(acc[co][3], acc[co][3], qsum);
        float2 fs = u2f(ssum), fq = u2f(qsum);
        float s = fs.x + fs.y;
        float q = fq.x + fq.y;
#pragma unroll
        for (int o = G / 2; o > 0; o >>= 1) {
            s += __shfl_down_sync(0xffffffffu, s, o, G);
            q += __shfl_down_sync(0xffffffffu, q, o, G);
        }
        if (h == 0) {
            size_t pidx = ((size_t)(km * COUT + co0 + co) * B_ + b) * NB
                          + blockIdx.x;
            psum[pidx] = s;
            psq[pidx] = q;
        }
    }
}

// ---------------------------------------------------------------------------
// 4. BN statistics finalize: one block per (km, ch), sums B*nblk partials.
// ---------------------------------------------------------------------------
__global__ __launch_bounds__(256) void stats_fin_kernel(int Cout, int nblk) {
    int co = blockIdx.x, km = blockIdx.y;
    int tid = threadIdx.x;
    const float* ps = d_psum + (size_t)(km * Cout + co) * B_ * nblk;
    const float* pq = d_psq + (size_t)(km * Cout + co) * B_ * nblk;
    float s = 0.f, q = 0.f;
    for (int i = tid; i < B_ * nblk; i += 256) {
        s += ps[i];
        q += pq[i];
    }
    __shared__ float r1[256], r2[256];
    r1[tid] = s; r2[tid] = q;
    __syncthreads();
    for (int o = 128; o > 0; o >>= 1) {
        if (tid < o) { r1[tid] += r1[tid + o]; r2[tid] += r2[tid + o]; }
        __syncthreads();
    }
    if (tid == 0) {
        float cnt = (float)B_ * (float)T_;
        float m = r1[0] / cnt;
        float v = r2[0] / cnt - m * m;
        d_mean[km * 64 + co] = m;
        d_rstd[km * 64 + co] = rsqrtf(v + EPS_);
    }
}

// ---------------------------------------------------------------------------
// 5. BN+ReLU + mean-pool over T -> feats (B, K*FEAT)
// ---------------------------------------------------------------------------
__global__ __launch_bounds__(256) void pool_kernel(
    const float* __restrict__ h,
    const float* __restrict__ bng, const float* __restrict__ bnb) {
    int co = blockIdx.x, b = blockIdx.y, km = blockIdx.z;
    int tid = threadIdx.x;
    float a = bng[km * FEAT_ + co] * d_rstd[km * 64 + co];
    float cc = bnb[km * FEAT_ + co] - a * d_mean[km * 64 + co];
    const float* row = h + (((size_t)km * B_ + b) * FEAT_ + co) * T_;
    float s = 0.f;
    for (int t = tid; t < T_; t += 256)
        s += fmaxf(fmaf(a, row[t], cc), 0.f);
    __shared__ float r[256];
    r[tid] = s;
    __syncthreads();
    for (int o = 128; o > 0; o >>= 1) {
        if (tid < o) r[tid] += r[tid + o];
        __syncthreads();
    }
    if (tid == 0)
        d_feats[(size_t)b * (K_ * FEAT_) + km * FEAT_ + co] = r[0] * (1.0f / T_);
}

// ---------------------------------------------------------------------------
// 6. Classifier: relu(fused @ fc1^T + b1) @ fc2^T + b2
// ---------------------------------------------------------------------------
__global__ __launch_bounds__(128) void classifier_kernel(
    const float* __restrict__ w1, const float* __restrict__ b1,
    const float* __restrict__ w2, const float* __restrict__ b2,
    float* __restrict__ out) {
    int b = blockIdx.x;
    int j = threadIdx.x;
    __shared__ float sf[K_ * FEAT_];
    __shared__ float sh[HID_];
    for (int i = j; i < K_ * FEAT_; i += 128) sf[i] = d_feats[(size_t)b * (K_ * FEAT_) + i];
    __syncthreads();
    float a = b1[j];
    const float* wr = w1 + (size_t)j * (K_ * FEAT_);
#pragma unroll 8
    for (int i = 0; i < K_ * FEAT_; i++) a = fmaf(sf[i], wr[i], a);
    sh[j] = fmaxf(a, 0.f);
    __syncthreads();
    if (j < NCLS_) {
        float o = b2[j];
        const float* w2r = w2 + (size_t)j * HID_;
#pragma unroll 8
        for (int i = 0; i < HID_; i++) o = fmaf(sh[i], w2r[i], o);
        out[b * NCLS_ + j] = o;
    }
}

// ---------------------------------------------------------------------------
// Launch
// ---------------------------------------------------------------------------
extern "C" void kernel_launch(void* const* d_in, const int* in_sizes, int n_in,
                              void* d_out, int out_size) {
    const float* x         = (const float*)d_in[0];
    const float* log_alpha = (const float*)d_in[1];
    const float* raw_tau   = (const float*)d_in[2];
    const float* raw_omega = (const float*)d_in[3];
    const float* conv_w1   = (const float*)d_in[4];
    const float* conv_b1   = (const float*)d_in[5];
    const float* bn_g1     = (const float*)d_in[6];
    const float* bn_b1     = (const float*)d_in[7];
    const float* conv_w2   = (const float*)d_in[8];
    const float* conv_b2   = (const float*)d_in[9];
    const float* bn_g2     = (const float*)d_in[10];
    const float* bn_b2     = (const float*)d_in[11];
    const float* conv_w3   = (const float*)d_in[12];
    const float* conv_b3   = (const float*)d_in[13];
    const float* bn_g3     = (const float*)d_in[14];
    const float* bn_b3     = (const float*)d_in[15];
    const float* fc1_w     = (const float*)d_in[16];
    const float* fc1_b     = (const float*)d_in[17];
    const float* fc2_w     = (const float*)d_in[18];
    const float* fc2_b     = (const float*)d_in[19];
    float* out = (float*)d_out;

    float *p_modes, *p_h1, *p_h2, *p_h3, *p_mean, *p_rstd, *p_psum, *p_psq;
    ull *p_w21, *p_w22, *p_w23;
    cudaGetSymbolAddress((void**)&p_modes, d_modes);
    cudaGetSymbolAddress((void**)&p_h1, d_h1);
    cudaGetSymbolAddress((void**)&p_h2, d_h2);
    cudaGetSymbolAddress((void**)&p_h3, d_h3);
    cudaGetSymbolAddress((void**)&p_mean, d_mean);
    cudaGetSymbolAddress((void**)&p_rstd, d_rstd);
    cudaGetSymbolAddress((void**)&p_psum, d_psum);
    cudaGetSymbolAddress((void**)&p_psq, d_psq);
    cudaGetSymbolAddress((void**)&p_w21, d_w2_1);
    cudaGetSymbolAddress((void**)&p_w22, d_w2_2);
    cudaGetSymbolAddress((void**)&p_w23, d_w2_3);

    // #1 UVMD filters
    g_kernel<<<(TR_ + 127) / 128, 128>>>(log_alpha, raw_tau, raw_omega);
    // #2 FFT -> filter -> iFFT -> modes
    uvmd_kernel<<<B_ * C_, 256>>>(x);
    // #3 weight repack
    wprep_kernel<<<(K_ * 64 * 64 * 3 + 255) / 256, 256>>>(conv_w1, conv_w2, conv_w3);

    // #4 conv1: 12 -> 32, k=7, CO=4, TILE=256 (8 blocks/T)
    conv_kernel<12, 32, 7, 4, 256, 8><<<dim3(8, B_, K_), 256>>>(
        p_modes, p_w21, conv_b1, nullptr, nullptr, nullptr, nullptr,
        p_h1, p_psum, p_psq, 0);
    // #5 finalize BN1
    stats_fin_kernel<<<dim3(32, K_), 256>>>(32, 8);
    // #6 conv2: 32 -> 64, k=5, CO=4, TILE=128
    conv_kernel<32, 64, 5, 4, 128, 16><<<dim3(16, B_, K_), 256>>>(
        p_h1, p_w22, conv_b2, bn_g1, bn_b1, p_mean, p_rstd,
        p_h2, p_psum, p_psq, 1);
    stats_fin_kernel<<<dim3(64, K_), 256>>>(64, 16);
    // conv3: 64 -> 64, k=3, CO=4, TILE=128
    conv_kernel<64, 64, 3, 4, 128, 16><<<dim3(16, B_, K_), 256>>>(
        p_h2, p_w23, conv_b3, bn_g2, bn_b2, p_mean, p_rstd,
        p_h3, p_psum, p_psq, 1);
    stats_fin_kernel<<<dim3(64, K_), 256>>>(64, 16);
    // BN3+ReLU + mean pool
    pool_kernel<<<dim3(FEAT_, B_, K_), 256>>>(p_h3, bn_g3, bn_b3);
    // classifier
    classifier_kernel<<<B_, HID_>>>(fc1_w, fc1_b, fc2_w, fc2_b, out);
}